// round 4
// baseline (speedup 1.0000x reference)
#include <cuda_runtime.h>
#include <cstdint>

#define DINLINE __device__ __forceinline__

// ============================ helpers ============================
DINLINE uint32_t smem_u32(const void* p) {
    uint32_t a;
    asm("{ .reg .u64 t; cvta.to.shared.u64 t, %1; cvt.u32.u64 %0, t; }" : "=r"(a) : "l"(p));
    return a;
}

DINLINE void cpa16(uint32_t dst, const void* src) {
    asm volatile("cp.async.cg.shared.global [%0], [%1], 16;"
                 :: "r"(dst), "l"(__cvta_generic_to_global(src)) : "memory");
}
#define CPA_COMMIT() asm volatile("cp.async.commit_group;" ::: "memory")
#define CPA_WAIT(n)  asm volatile("cp.async.wait_group %0;" :: "n"(n) : "memory")

// m16n8k8 tf32 HMMA (target-portable, sm_80+)
DINLINE void mma8(float* d, uint32_t a0, uint32_t a1, uint32_t a2, uint32_t a3,
                  uint32_t b0, uint32_t b1) {
    asm volatile("mma.sync.aligned.m16n8k8.row.col.f32.tf32.tf32.f32 "
                 "{%0,%1,%2,%3}, {%4,%5,%6,%7}, {%8,%9}, {%0,%1,%2,%3};"
                 : "+f"(d[0]), "+f"(d[1]), "+f"(d[2]), "+f"(d[3])
                 : "r"(a0), "r"(a1), "r"(a2), "r"(a3), "r"(b0), "r"(b1));
}

// round-to-nearest tf32 (zero-mean quantization error)
DINLINE float tf32rn(float f) {
    uint32_t o;
    asm("cvt.rna.tf32.f32 %0, %1;" : "=r"(o) : "f"(f));
    return __uint_as_float(o);
}
DINLINE uint32_t fbits(float f) { return __float_as_uint(f); }

// ============================ constants ============================
static constexpr int NN = 8192;
static constexpr int DD = 256;

// GEMM1: BM=128, BN=256, BK=32, 3 stages, 512 threads (16 warps, 4x4, warp tile 32x64)
static constexpr int STAGE1_FLOATS = (128 + 256) * 32;          // 12288
static constexpr int SMEM1_BYTES   = 3 * STAGE1_FLOATS * 4;     // 147456
// GEMM2: BM=64, BN=256, BK=32 single-buffer, 256 threads (8 warps, 2x4, warp tile 32x64)
static constexpr int SMEM2_BYTES   = (64 + 256) * 32 * 4;       // 40960

// scratch (allocation-free contract: __device__ globals)
__device__ float d_dis[NN];                 // (1 + rowsum(adj))^{-1/2}
__device__ float d_xT[(long)DD * NN];       // xT[c][n] = tf32rn(dis[n] * x[n][c])
__device__ float d_part[2L * NN * DD];      // split-K partials of adj @ X'
__device__ float d_Wr[DD * DD];             // tf32rn(W)

// ============================ K0: row sums ============================
__global__ void rowsum_kernel(const float* __restrict__ adj) {
    __shared__ float red[256];
    long i = blockIdx.x;
    const float4* row = (const float4*)(adj + i * (long)NN);
    float s = 0.f;
#pragma unroll
    for (int u = 0; u < 8; u++) {
        float4 v = row[threadIdx.x + u * 256];
        s += (v.x + v.y) + (v.z + v.w);
    }
    red[threadIdx.x] = s;
    __syncthreads();
    for (int o = 128; o > 0; o >>= 1) {
        if (threadIdx.x < o) red[threadIdx.x] += red[threadIdx.x + o];
        __syncthreads();
    }
    if (threadIdx.x == 0) d_dis[i] = rsqrtf(1.0f + red[0]);
}

// ============================ K0b: W -> tf32rn copy ============================
__global__ void wcopy_kernel(const float* __restrict__ W) {
    int idx = (blockIdx.x * 256 + threadIdx.x) * 4;
    float4 v = *(const float4*)(W + idx);
    v.x = tf32rn(v.x); v.y = tf32rn(v.y); v.z = tf32rn(v.z); v.w = tf32rn(v.w);
    *(float4*)(d_Wr + idx) = v;
}

// ============================ K1: xT[c][n] = rn(dis[n]*x[n][c]) ============================
__global__ void txpose_kernel(const float* __restrict__ x) {
    __shared__ float t[32][33];
    int n0 = blockIdx.x * 32, c0 = blockIdx.y * 32;
    int tx = threadIdx.x, ty = threadIdx.y;
#pragma unroll
    for (int u = 0; u < 4; u++) {
        int n = n0 + ty + u * 8;
        t[ty + u * 8][tx] = x[(long)n * DD + c0 + tx] * d_dis[n];
    }
    __syncthreads();
#pragma unroll
    for (int u = 0; u < 4; u++) {
        int c = c0 + ty + u * 8;
        d_xT[(long)c * NN + n0 + tx] = tf32rn(t[tx][ty + u * 8]);
    }
}

// ============================================================================
// Core per-stage fragment math: warp tile 32x64 (f<2, g<8), BN=256.
//   A SMEM: [8][AROWS][4] floats -> word(k,m) = ((k>>2)*AROWS + m)*4 + (k&3)
//   B SMEM: [8][256][4]   floats -> word(k,n) = ((k>>2)*256   + n)*4 + (k&3)
// Every fragment load is a linear 128B warp access (conflict-free).
// ============================================================================
template <int AROWS>
DINLINE void compute_stage2(const float* __restrict__ A, const float* __restrict__ B,
                            int mbase, int wn, int lane, float acc[2][8][4]) {
    const int g4 = lane >> 2;
    const int c4 = lane & 3;
#pragma unroll
    for (int k8 = 0; k8 < 4; k8++) {
        const int k4a = k8 * 2, k4b = k8 * 2 + 1;
        uint32_t b[8][2];
#pragma unroll
        for (int g = 0; g < 8; g++) {
            int n = wn * 64 + g * 8 + g4;
            b[g][0] = fbits(B[(k4a * 256 + n) * 4 + c4]);
            b[g][1] = fbits(B[(k4b * 256 + n) * 4 + c4]);
        }
#pragma unroll
        for (int f = 0; f < 2; f++) {
            int m = mbase + f * 16 + g4;
            uint32_t a0 = fbits(A[(k4a * AROWS + m) * 4 + c4]);
            uint32_t a1 = fbits(A[(k4a * AROWS + m + 8) * 4 + c4]);
            uint32_t a2 = fbits(A[(k4b * AROWS + m) * 4 + c4]);
            uint32_t a3 = fbits(A[(k4b * AROWS + m + 8) * 4 + c4]);
#pragma unroll
            for (int g = 0; g < 8; g++)
                mma8(acc[f][g], a0, a1, a2, a3, b[g][0], b[g][1]);
        }
    }
}

// ============================ K2: GEMM1 part[ks] = adj[m0:,ksK] @ X'[ksK,:] ============================
__global__ void __launch_bounds__(512, 1) gemm1_kernel(const float* __restrict__ adj) {
    extern __shared__ float smem[];
    const int tid = threadIdx.x, lane = tid & 31, wid = tid >> 5;
    const int wm = wid & 3, wn = wid >> 2;          // 4x4 warp grid
    const int ks = blockIdx.x & 1;
    const long m0 = (long)(blockIdx.x >> 1) * 128;
    const long kb = (long)ks * 4096;
    const int NK = 128;                              // 4096 / 32

    const int j = tid & 7;                           // k4 chunk 0..7
    const int r = tid >> 3;                          // 0..63

    float acc[2][8][4];
#pragma unroll
    for (int f = 0; f < 2; f++)
#pragma unroll
        for (int g = 0; g < 8; g++)
#pragma unroll
            for (int q = 0; q < 4; q++) acc[f][g][q] = 0.f;

    auto load_stage = [&](int s, long k0) {
        float* As = smem + s * STAGE1_FLOATS;
        float* Bs = As + 4096;
        const uint32_t abase = smem_u32(As), bbase = smem_u32(Bs);
#pragma unroll
        for (int u = 0; u < 2; u++) {
            int row = r + u * 64;
            cpa16(abase + (uint32_t)((j * 128 + row) * 16),
                  adj + (m0 + row) * (long)NN + k0 + j * 4);
        }
#pragma unroll
        for (int u = 0; u < 4; u++) {
            int n = r + u * 64;
            cpa16(bbase + (uint32_t)((j * 256 + n) * 16),
                  d_xT + (long)n * NN + k0 + j * 4);
        }
    };

    // prologue: stages 0,1
    load_stage(0, kb);       CPA_COMMIT();
    load_stage(1, kb + 32);  CPA_COMMIT();

#pragma unroll 1
    for (int kt = 0; kt < NK; kt++) {
        CPA_WAIT(1);
        __syncthreads();
        if (kt + 2 < NK) load_stage((kt + 2) % 3, kb + (long)(kt + 2) * 32);
        CPA_COMMIT();
        const float* As = smem + (kt % 3) * STAGE1_FLOATS;
        compute_stage2<128>(As, As + 4096, wm * 32, wn, lane, acc);
    }

    // epilogue: write split-K partials
    float* pbase = d_part + (long)ks * NN * DD;
#pragma unroll
    for (int f = 0; f < 2; f++) {
        int row = wm * 32 + f * 16 + (lane >> 2);
#pragma unroll
        for (int g = 0; g < 8; g++) {
            int col = wn * 64 + g * 8 + (lane & 3) * 2;
            float2 lo = make_float2(acc[f][g][0], acc[f][g][1]);
            float2 hi = make_float2(acc[f][g][2], acc[f][g][3]);
            *(float2*)(pbase + (m0 + row) * DD + col) = lo;
            *(float2*)(pbase + (m0 + row + 8) * DD + col) = hi;
        }
    }
}

// ============================ K3: GEMM2 out = relu(diag(d) * ((part0+part1+diag(d)x) @ Wr^T)) ============================
__global__ void __launch_bounds__(256, 1) gemm2_kernel(const float* __restrict__ x,
                                                       float* __restrict__ out) {
    extern __shared__ float smem[];
    const int tid = threadIdx.x, lane = tid & 31, wid = tid >> 5;
    const int wm = wid & 1, wn = wid >> 1;            // 2x4 warp grid
    const long m0 = (long)blockIdx.x * 64;
    const int j = tid & 7, r = tid >> 3;              // r: 0..31

    float acc[2][8][4];
#pragma unroll
    for (int f = 0; f < 2; f++)
#pragma unroll
        for (int g = 0; g < 8; g++)
#pragma unroll
            for (int q = 0; q < 4; q++) acc[f][g][q] = 0.f;

    float* As = smem;                 // [8][64][4]
    float* Bs = smem + 64 * 32;       // [8][256][4]
    const uint32_t bbase = smem_u32(Bs);

#pragma unroll 1
    for (int st = 0; st < 8; st++) {
        const int k0 = st * 32;
        __syncthreads();   // previous stage's compute done before overwrite
        // B chunk: W rows (output features), cols k0..k0+31
#pragma unroll
        for (int u = 0; u < 8; u++) {
            int n = r + u * 32;
            cpa16(bbase + (uint32_t)((j * 256 + n) * 16), d_Wr + (long)n * DD + k0 + j * 4);
        }
        CPA_COMMIT();
        // A chunk: part0 + part1 + dis*x, RN-rounded to tf32
#pragma unroll
        for (int u = 0; u < 2; u++) {
            int row = r + u * 32;
            long i = m0 + row;
            float di = d_dis[i];
            float4 p0 = *(const float4*)(d_part + i * DD + k0 + j * 4);
            float4 p1 = *(const float4*)(d_part + (long)NN * DD + i * DD + k0 + j * 4);
            float4 xv = *(const float4*)(x + i * DD + k0 + j * 4);
            float4 v;
            v.x = tf32rn(p0.x + p1.x + di * xv.x);
            v.y = tf32rn(p0.y + p1.y + di * xv.y);
            v.z = tf32rn(p0.z + p1.z + di * xv.z);
            v.w = tf32rn(p0.w + p1.w + di * xv.w);
            *(float4*)(As + (j * 64 + row) * 4) = v;
        }
        CPA_WAIT(0);
        __syncthreads();
        compute_stage2<64>(As, Bs, wm * 32, wn, lane, acc);
    }

    // epilogue: relu(dis * acc)
#pragma unroll
    for (int f = 0; f < 2; f++) {
        int row = wm * 32 + f * 16 + (lane >> 2);
        float d0 = d_dis[m0 + row];
        float d8 = d_dis[m0 + row + 8];
#pragma unroll
        for (int g = 0; g < 8; g++) {
            int col = wn * 64 + g * 8 + (lane & 3) * 2;
            float2 lo, hi;
            lo.x = fmaxf(d0 * acc[f][g][0], 0.f);
            lo.y = fmaxf(d0 * acc[f][g][1], 0.f);
            hi.x = fmaxf(d8 * acc[f][g][2], 0.f);
            hi.y = fmaxf(d8 * acc[f][g][3], 0.f);
            *(float2*)(out + (m0 + row) * DD + col) = lo;
            *(float2*)(out + (m0 + row + 8) * DD + col) = hi;
        }
    }
}

// ============================ host ============================
extern "C" void kernel_launch(void* const* d_in, const int* in_sizes, int n_in,
                              void* d_out, int out_size) {
    const float* x   = (const float*)d_in[0];   // [8192, 256]
    const float* adj = (const float*)d_in[1];   // [8192, 8192]
    const float* W   = (const float*)d_in[2];   // [256, 256]
    float* out = (float*)d_out;

    cudaFuncSetAttribute(gemm1_kernel, cudaFuncAttributeMaxDynamicSharedMemorySize, SMEM1_BYTES);
    cudaFuncSetAttribute(gemm2_kernel, cudaFuncAttributeMaxDynamicSharedMemorySize, SMEM2_BYTES);

    rowsum_kernel<<<NN, 256>>>(adj);
    wcopy_kernel<<<DD * DD / 1024, 256>>>(W);
    txpose_kernel<<<dim3(NN / 32, DD / 32), dim3(32, 8)>>>(x);
    gemm1_kernel<<<128, 512, SMEM1_BYTES>>>(adj);
    gemm2_kernel<<<128, 256, SMEM2_BYTES>>>(x, out);
}

// round 5
// speedup vs baseline: 2.1825x; 2.1825x over previous
#include <cuda_runtime.h>
#include <cuda_fp16.h>
#include <cstdint>

#define DINLINE __device__ __forceinline__

// ============================ helpers ============================
DINLINE uint32_t smem_u32(const void* p) {
    uint32_t a;
    asm("{ .reg .u64 t; cvta.to.shared.u64 t, %1; cvt.u32.u64 %0, t; }" : "=r"(a) : "l"(p));
    return a;
}

DINLINE void cpa16(uint32_t dst, const void* src) {
    asm volatile("cp.async.cg.shared.global [%0], [%1], 16;"
                 :: "r"(dst), "l"(__cvta_generic_to_global(src)) : "memory");
}
#define CPA_COMMIT() asm volatile("cp.async.commit_group;" ::: "memory")
#define CPA_WAIT(n)  asm volatile("cp.async.wait_group %0;" :: "n"(n) : "memory")

// m16n8k16 fp16 HMMA, fp32 accumulate (target-portable, sm_80+)
DINLINE void mma16(float* d, uint32_t a0, uint32_t a1, uint32_t a2, uint32_t a3,
                   uint32_t b0, uint32_t b1) {
    asm volatile("mma.sync.aligned.m16n8k16.row.col.f32.f16.f16.f32 "
                 "{%0,%1,%2,%3}, {%4,%5,%6,%7}, {%8,%9}, {%0,%1,%2,%3};"
                 : "+f"(d[0]), "+f"(d[1]), "+f"(d[2]), "+f"(d[3])
                 : "r"(a0), "r"(a1), "r"(a2), "r"(a3), "r"(b0), "r"(b1));
}

// m16n8k8 tf32 HMMA (kept for gemm2)
DINLINE void mma8(float* d, uint32_t a0, uint32_t a1, uint32_t a2, uint32_t a3,
                  uint32_t b0, uint32_t b1) {
    asm volatile("mma.sync.aligned.m16n8k8.row.col.f32.tf32.tf32.f32 "
                 "{%0,%1,%2,%3}, {%4,%5,%6,%7}, {%8,%9}, {%0,%1,%2,%3};"
                 : "+f"(d[0]), "+f"(d[1]), "+f"(d[2]), "+f"(d[3])
                 : "r"(a0), "r"(a1), "r"(a2), "r"(a3), "r"(b0), "r"(b1));
}

DINLINE void lds64(uint32_t& lo, uint32_t& hi, uint32_t addr) {
    asm volatile("ld.shared.v2.b32 {%0,%1}, [%2];" : "=r"(lo), "=r"(hi) : "r"(addr));
}

// round-to-nearest tf32
DINLINE float tf32rn(float f) {
    uint32_t o;
    asm("cvt.rna.tf32.f32 %0, %1;" : "=r"(o) : "f"(f));
    return __uint_as_float(o);
}
DINLINE uint32_t fbits(float f) { return __float_as_uint(f); }
DINLINE uint32_t h2u(__half2 h) { return *(uint32_t*)&h; }

// ============================ constants ============================
static constexpr int NN = 8192;
static constexpr int DD = 256;

// GEMM1 (fp16): BM=128, BN=256, BK=32, 3 stages, 512 threads (16 warps, 4x4, warp tile 32x64)
// stage = A 8KB + B 16KB = 24KB
static constexpr int STAGE1_BYTES = 24576;
static constexpr int SMEM1_BYTES  = 3 * STAGE1_BYTES;           // 73728
// GEMM2 (tf32, unchanged): BM=64, BN=256, BK=32 single-buffer, 256 threads
static constexpr int SMEM2_BYTES  = (64 + 256) * 32 * 4;        // 40960

// scratch (allocation-free contract: __device__ globals)
__device__ float d_dis[NN];                    // (1 + rowsum(adj))^{-1/2}
__device__ uint4 d_adjh[(long)NN * NN / 8];    // adj as fp16, fragment-word layout (128MB)
__device__ uint4 d_xTh[(long)NN * DD / 8];     // X'^T as fp16, fragment-word layout (4MB)
__device__ float d_part[2L * NN * DD];         // split-K partials of adj @ X'
__device__ float d_Wr[DD * DD];                // tf32rn(W)

// ============================================================================
// K0: fused rowsum + adj->fp16 conversion into fragment-word layout.
// Word layout per row m: 512 k-chunks of 16; chunk c stores 4 x 8B words:
//   word j = fp16{ k=16c+2j, 16c+2j+1 | k=16c+2j+8, 16c+2j+9 }
// uint4 idx (m*512 + c)*2 + q holds words {j=2q, j=2q+1}.
// ============================================================================
__global__ void prepass_kernel(const float* __restrict__ adj) {
    __shared__ float red[256];
    const long m = blockIdx.x;
    const int t = threadIdx.x, lane = t & 31;
    const float4* row = (const float4*)(adj + m * (long)NN);   // 2048 float4
    uint4* outrow = d_adjh + m * 1024;
    float s = 0.f;
#pragma unroll
    for (int u = 0; u < 8; u++) {
        int fi = u * 256 + t;                 // float4 index, covers k = 4*fi..4*fi+3
        float4 v = row[fi];
        s += (v.x + v.y) + (v.z + v.w);
        // partner lane^2 holds k+8 (or k-8)
        float px = __shfl_xor_sync(0xFFFFFFFFu, v.x, 2);
        float py = __shfl_xor_sync(0xFFFFFFFFu, v.y, 2);
        float pz = __shfl_xor_sync(0xFFFFFFFFu, v.z, 2);
        float pw = __shfl_xor_sync(0xFFFFFFFFu, v.w, 2);
        if ((lane & 2) == 0) {                // low-k quarters produce the words
            uint4 o;
            o.x = h2u(__float22half2_rn(make_float2(v.x, v.y)));
            o.y = h2u(__float22half2_rn(make_float2(px, py)));
            o.z = h2u(__float22half2_rn(make_float2(v.z, v.w)));
            o.w = h2u(__float22half2_rn(make_float2(pz, pw)));
            int chunk = fi >> 2, q = fi & 1;
            outrow[chunk * 2 + q] = o;
        }
    }
    red[t] = s;
    __syncthreads();
    for (int o = 128; o > 0; o >>= 1) {
        if (t < o) red[t] += red[t + o];
        __syncthreads();
    }
    if (t == 0) d_dis[m] = rsqrtf(1.0f + red[0]);
}

// ============================ K0b: W -> tf32rn copy (for gemm2) ============================
__global__ void wcopy_kernel(const float* __restrict__ W) {
    int idx = (blockIdx.x * 256 + threadIdx.x) * 4;
    float4 v = *(const float4*)(W + idx);
    v.x = tf32rn(v.x); v.y = tf32rn(v.y); v.z = tf32rn(v.z); v.w = tf32rn(v.w);
    *(float4*)(d_Wr + idx) = v;
}

// ============================ K1: X'^T -> fp16 fragment-word layout ============================
// d_xTh word64 idx = (C*256 + feature)*4 + j, C = node-chunk (node k-dim of GEMM1),
// word j = fp16{ dis*x at nodes 16C+2j, +1 | 16C+2j+8, +9 } for that feature.
__global__ void txpose_kernel(const float* __restrict__ x) {
    __shared__ float t[32][33];
    int n0 = blockIdx.x * 32, c0 = blockIdx.y * 32;
    int tx = threadIdx.x, ty = threadIdx.y;
#pragma unroll
    for (int u = 0; u < 4; u++) {
        int n = n0 + ty + u * 8;
        t[ty + u * 8][tx] = x[(long)n * DD + c0 + tx] * d_dis[n];
    }
    __syncthreads();
    int w = ty * 32 + tx;
    int fl = w >> 3, sub = w & 7, cq = sub >> 2, j = sub & 3;
    int l0 = cq * 16 + 2 * j;
    uint2 o;
    o.x = h2u(__float22half2_rn(make_float2(t[l0][fl],     t[l0 + 1][fl])));
    o.y = h2u(__float22half2_rn(make_float2(t[l0 + 8][fl], t[l0 + 9][fl])));
    int C = (n0 >> 4) + cq;
    ((uint2*)d_xTh)[(C * 256 + c0 + fl) * 4 + j] = o;
}

// ============================ K2: GEMM1 (fp16) part[ks] = adj[m0:,ksK] @ X'[ksK,:] ============================
__global__ void __launch_bounds__(512, 1) gemm1_kernel() {
    extern __shared__ char smem[];
    const uint32_t sbase = smem_u32(smem);
    const int tid = threadIdx.x, lane = tid & 31, wid = tid >> 5;
    const int wm = wid & 3, wn = wid >> 2;          // 4x4 warp grid, warp tile 32x64
    const int g4 = lane >> 2, c4 = lane & 3;
    const int ks = blockIdx.x & 1;
    const long m0 = (long)(blockIdx.x >> 1) * 128;
    const int NK = 128;                              // 4096 / 32

    const char* asrc = ((const char*)d_adjh) + m0 * 16384 + (long)ks * 8192;
    const char* bsrc = ((const char*)d_xTh) + (long)ks * 2097152;

    // per-thread cp.async coords for A: stage A = 512 x 16B
    const int a_c = tid >> 8, a_m = (tid >> 1) & 127, a_jh = tid & 1;

    float acc[2][8][4];
#pragma unroll
    for (int f = 0; f < 2; f++)
#pragma unroll
        for (int g = 0; g < 8; g++)
#pragma unroll
            for (int q = 0; q < 4; q++) acc[f][g][q] = 0.f;

    auto load_stage = [&](int s, int kt) {
        const uint32_t As = sbase + s * STAGE1_BYTES;
        const uint32_t Bs = As + 8192;
        cpa16(As + tid * 16,
              asrc + (long)a_m * 16384 + kt * 64 + a_c * 32 + a_jh * 16);
        cpa16(Bs + tid * 16,        bsrc + (long)kt * 16384 + tid * 16);
        cpa16(Bs + tid * 16 + 8192, bsrc + (long)kt * 16384 + tid * 16 + 8192);
    };

    load_stage(0, 0);  CPA_COMMIT();
    load_stage(1, 1);  CPA_COMMIT();

#pragma unroll 1
    for (int kt = 0; kt < NK; kt++) {
        CPA_WAIT(1);
        __syncthreads();
        if (kt + 2 < NK) load_stage((kt + 2) % 3, kt + 2);
        CPA_COMMIT();
        const uint32_t As = sbase + (kt % 3) * STAGE1_BYTES;
        const uint32_t Bs = As + 8192;
        // two K=16 chunks per stage
#pragma unroll
        for (int c = 0; c < 2; c++) {
            uint32_t b[8][2];
#pragma unroll
            for (int g = 0; g < 8; g++)
                lds64(b[g][0], b[g][1], Bs + (c * 256 + wn * 64 + g * 8 + g4) * 32 + c4 * 8);
#pragma unroll
            for (int f = 0; f < 2; f++) {
                const int r = wm * 32 + f * 16 + g4;
                uint32_t a0, a1, a2, a3;
                lds64(a0, a2, As + (c * 128 + r) * 32 + c4 * 8);
                lds64(a1, a3, As + (c * 128 + r + 8) * 32 + c4 * 8);
#pragma unroll
                for (int g = 0; g < 8; g++)
                    mma16(acc[f][g], a0, a1, a2, a3, b[g][0], b[g][1]);
            }
        }
    }

    // epilogue: write split-K partials (fp32)
    float* pbase = d_part + (long)ks * NN * DD;
#pragma unroll
    for (int f = 0; f < 2; f++) {
        int row = wm * 32 + f * 16 + g4;
#pragma unroll
        for (int g = 0; g < 8; g++) {
            int col = wn * 64 + g * 8 + c4 * 2;
            float2 lo = make_float2(acc[f][g][0], acc[f][g][1]);
            float2 hi = make_float2(acc[f][g][2], acc[f][g][3]);
            *(float2*)(pbase + (m0 + row) * DD + col) = lo;
            *(float2*)(pbase + (m0 + row + 8) * DD + col) = hi;
        }
    }
}

// ============================================================================
// GEMM2 core (tf32, proven): warp tile 32x64, k4-interleaved fp32 SMEM.
// ============================================================================
template <int AROWS>
DINLINE void compute_stage2(const float* __restrict__ A, const float* __restrict__ B,
                            int mbase, int wn, int lane, float acc[2][8][4]) {
    const int g4 = lane >> 2;
    const int c4 = lane & 3;
#pragma unroll
    for (int k8 = 0; k8 < 4; k8++) {
        const int k4a = k8 * 2, k4b = k8 * 2 + 1;
        uint32_t b[8][2];
#pragma unroll
        for (int g = 0; g < 8; g++) {
            int n = wn * 64 + g * 8 + g4;
            b[g][0] = fbits(B[(k4a * 256 + n) * 4 + c4]);
            b[g][1] = fbits(B[(k4b * 256 + n) * 4 + c4]);
        }
#pragma unroll
        for (int f = 0; f < 2; f++) {
            int m = mbase + f * 16 + g4;
            uint32_t a0 = fbits(A[(k4a * AROWS + m) * 4 + c4]);
            uint32_t a1 = fbits(A[(k4a * AROWS + m + 8) * 4 + c4]);
            uint32_t a2 = fbits(A[(k4b * AROWS + m) * 4 + c4]);
            uint32_t a3 = fbits(A[(k4b * AROWS + m + 8) * 4 + c4]);
#pragma unroll
            for (int g = 0; g < 8; g++)
                mma8(acc[f][g], a0, a1, a2, a3, b[g][0], b[g][1]);
        }
    }
}

// ============================ K3: GEMM2 out = relu(diag(d) * ((part0+part1+diag(d)x) @ Wr^T)) ============================
__global__ void __launch_bounds__(256, 1) gemm2_kernel(const float* __restrict__ x,
                                                       float* __restrict__ out) {
    extern __shared__ float smemf[];
    const int tid = threadIdx.x, lane = tid & 31, wid = tid >> 5;
    const int wm = wid & 1, wn = wid >> 1;            // 2x4 warp grid
    const long m0 = (long)blockIdx.x * 64;
    const int j = tid & 7, r = tid >> 3;              // r: 0..31

    float acc[2][8][4];
#pragma unroll
    for (int f = 0; f < 2; f++)
#pragma unroll
        for (int g = 0; g < 8; g++)
#pragma unroll
            for (int q = 0; q < 4; q++) acc[f][g][q] = 0.f;

    float* As = smemf;                 // [8][64][4]
    float* Bs = smemf + 64 * 32;       // [8][256][4]
    const uint32_t bbase = smem_u32(Bs);

#pragma unroll 1
    for (int st = 0; st < 8; st++) {
        const int k0 = st * 32;
        __syncthreads();
#pragma unroll
        for (int u = 0; u < 8; u++) {
            int n = r + u * 32;
            cpa16(bbase + (uint32_t)((j * 256 + n) * 16), d_Wr + (long)n * DD + k0 + j * 4);
        }
        CPA_COMMIT();
#pragma unroll
        for (int u = 0; u < 2; u++) {
            int row = r + u * 32;
            long i = m0 + row;
            float di = d_dis[i];
            float4 p0 = *(const float4*)(d_part + i * DD + k0 + j * 4);
            float4 p1 = *(const float4*)(d_part + (long)NN * DD + i * DD + k0 + j * 4);
            float4 xv = *(const float4*)(x + i * DD + k0 + j * 4);
            float4 v;
            v.x = tf32rn(p0.x + p1.x + di * xv.x);
            v.y = tf32rn(p0.y + p1.y + di * xv.y);
            v.z = tf32rn(p0.z + p1.z + di * xv.z);
            v.w = tf32rn(p0.w + p1.w + di * xv.w);
            *(float4*)(As + (j * 64 + row) * 4) = v;
        }
        CPA_WAIT(0);
        __syncthreads();
        compute_stage2<64>(As, Bs, wm * 32, wn, lane, acc);
    }

#pragma unroll
    for (int f = 0; f < 2; f++) {
        int row = wm * 32 + f * 16 + (lane >> 2);
        float d0 = d_dis[m0 + row];
        float d8 = d_dis[m0 + row + 8];
#pragma unroll
        for (int g = 0; g < 8; g++) {
            int col = wn * 64 + g * 8 + (lane & 3) * 2;
            float2 lo, hi;
            lo.x = fmaxf(d0 * acc[f][g][0], 0.f);
            lo.y = fmaxf(d0 * acc[f][g][1], 0.f);
            hi.x = fmaxf(d8 * acc[f][g][2], 0.f);
            hi.y = fmaxf(d8 * acc[f][g][3], 0.f);
            *(float2*)(out + (m0 + row) * DD + col) = lo;
            *(float2*)(out + (m0 + row + 8) * DD + col) = hi;
        }
    }
}

// ============================ host ============================
extern "C" void kernel_launch(void* const* d_in, const int* in_sizes, int n_in,
                              void* d_out, int out_size) {
    const float* x   = (const float*)d_in[0];   // [8192, 256]
    const float* adj = (const float*)d_in[1];   // [8192, 8192]
    const float* W   = (const float*)d_in[2];   // [256, 256]
    float* out = (float*)d_out;

    cudaFuncSetAttribute(gemm1_kernel, cudaFuncAttributeMaxDynamicSharedMemorySize, SMEM1_BYTES);
    cudaFuncSetAttribute(gemm2_kernel, cudaFuncAttributeMaxDynamicSharedMemorySize, SMEM2_BYTES);

    prepass_kernel<<<NN, 256>>>(adj);
    wcopy_kernel<<<DD * DD / 1024, 256>>>(W);
    txpose_kernel<<<dim3(NN / 32, DD / 32), dim3(32, 8)>>>(x);
    gemm1_kernel<<<128, 512, SMEM1_BYTES>>>();
    gemm2_kernel<<<128, 256, SMEM2_BYTES>>>(x, out);
}

// round 6
// speedup vs baseline: 2.3742x; 1.0878x over previous
#include <cuda_runtime.h>
#include <cuda_fp16.h>
#include <cstdint>

#define DINLINE __device__ __forceinline__

// ============================ helpers ============================
DINLINE uint32_t smem_u32(const void* p) {
    uint32_t a;
    asm("{ .reg .u64 t; cvta.to.shared.u64 t, %1; cvt.u32.u64 %0, t; }" : "=r"(a) : "l"(p));
    return a;
}

DINLINE void cpa16(uint32_t dst, const void* src) {
    asm volatile("cp.async.cg.shared.global [%0], [%1], 16;"
                 :: "r"(dst), "l"(__cvta_generic_to_global(src)) : "memory");
}
#define CPA_COMMIT() asm volatile("cp.async.commit_group;" ::: "memory")
#define CPA_WAIT(n)  asm volatile("cp.async.wait_group %0;" :: "n"(n) : "memory")

// m16n8k16 fp16 HMMA, fp32 accumulate (target-portable, sm_80+)
DINLINE void mma16(float* d, uint32_t a0, uint32_t a1, uint32_t a2, uint32_t a3,
                   uint32_t b0, uint32_t b1) {
    asm volatile("mma.sync.aligned.m16n8k16.row.col.f32.f16.f16.f32 "
                 "{%0,%1,%2,%3}, {%4,%5,%6,%7}, {%8,%9}, {%0,%1,%2,%3};"
                 : "+f"(d[0]), "+f"(d[1]), "+f"(d[2]), "+f"(d[3])
                 : "r"(a0), "r"(a1), "r"(a2), "r"(a3), "r"(b0), "r"(b1));
}

// m16n8k8 tf32 HMMA (kept for gemm2)
DINLINE void mma8(float* d, uint32_t a0, uint32_t a1, uint32_t a2, uint32_t a3,
                  uint32_t b0, uint32_t b1) {
    asm volatile("mma.sync.aligned.m16n8k8.row.col.f32.tf32.tf32.f32 "
                 "{%0,%1,%2,%3}, {%4,%5,%6,%7}, {%8,%9}, {%0,%1,%2,%3};"
                 : "+f"(d[0]), "+f"(d[1]), "+f"(d[2]), "+f"(d[3])
                 : "r"(a0), "r"(a1), "r"(a2), "r"(a3), "r"(b0), "r"(b1));
}

DINLINE void lds64(uint32_t& lo, uint32_t& hi, uint32_t addr) {
    asm volatile("ld.shared.v2.b32 {%0,%1}, [%2];" : "=r"(lo), "=r"(hi) : "r"(addr));
}

// round-to-nearest tf32
DINLINE float tf32rn(float f) {
    uint32_t o;
    asm("cvt.rna.tf32.f32 %0, %1;" : "=r"(o) : "f"(f));
    return __uint_as_float(o);
}
DINLINE uint32_t fbits(float f) { return __float_as_uint(f); }
DINLINE uint32_t h2u(__half2 h) { return *(uint32_t*)&h; }

// ============================ constants ============================
static constexpr int NN = 8192;
static constexpr int DD = 256;

// GEMM1 (fp16): BM=128, BN=256, BK=32, 3 stages, 256 threads (8 warps, 2x4, warp tile 64x64)
// stage = A 8KB + B 16KB = 24KB
static constexpr int STAGE1_BYTES = 24576;
static constexpr int SMEM1_BYTES  = 3 * STAGE1_BYTES;           // 73728
// GEMM2 (tf32): BM=64, BN=256, BK=32 single-buffer, 256 threads
static constexpr int SMEM2_BYTES  = (64 + 256) * 32 * 4;        // 40960

// scratch (allocation-free contract: __device__ globals)
__device__ float d_dis[NN];                    // (1 + rowsum(adj))^{-1/2}
__device__ uint4 d_adjh[(long)NN * NN / 8];    // adj as fp16, fragment-word layout (128MB)
__device__ uint4 d_xTh[(long)NN * DD / 8];     // X'^T as fp16, fragment-word layout (4MB)
__device__ float d_part[2L * NN * DD];         // split-K partials of adj @ X'
__device__ float d_Wr[DD * DD];                // tf32rn(W)

// ============================================================================
// K0: fused rowsum + adj->fp16 conversion into fragment-word layout.
// Word layout per row m: 512 k-chunks of 16; chunk c stores 4 x 8B words:
//   word j = fp16{ k=16c+2j, 16c+2j+1 | k=16c+2j+8, 16c+2j+9 }
// ============================================================================
__global__ void prepass_kernel(const float* __restrict__ adj) {
    __shared__ float red[256];
    const long m = blockIdx.x;
    const int t = threadIdx.x, lane = t & 31;
    const float4* row = (const float4*)(adj + m * (long)NN);   // 2048 float4
    uint4* outrow = d_adjh + m * 1024;
    float s = 0.f;
#pragma unroll
    for (int u = 0; u < 8; u++) {
        int fi = u * 256 + t;                 // float4 index, covers k = 4*fi..4*fi+3
        float4 v = row[fi];
        s += (v.x + v.y) + (v.z + v.w);
        float px = __shfl_xor_sync(0xFFFFFFFFu, v.x, 2);
        float py = __shfl_xor_sync(0xFFFFFFFFu, v.y, 2);
        float pz = __shfl_xor_sync(0xFFFFFFFFu, v.z, 2);
        float pw = __shfl_xor_sync(0xFFFFFFFFu, v.w, 2);
        if ((lane & 2) == 0) {
            uint4 o;
            o.x = h2u(__float22half2_rn(make_float2(v.x, v.y)));
            o.y = h2u(__float22half2_rn(make_float2(px, py)));
            o.z = h2u(__float22half2_rn(make_float2(v.z, v.w)));
            o.w = h2u(__float22half2_rn(make_float2(pz, pw)));
            int chunk = fi >> 2, q = fi & 1;
            outrow[chunk * 2 + q] = o;
        }
    }
    red[t] = s;
    __syncthreads();
    for (int o = 128; o > 0; o >>= 1) {
        if (t < o) red[t] += red[t + o];
        __syncthreads();
    }
    if (t == 0) d_dis[m] = rsqrtf(1.0f + red[0]);
}

// ============================ K0b: W -> tf32rn copy (for gemm2) ============================
__global__ void wcopy_kernel(const float* __restrict__ W) {
    int idx = (blockIdx.x * 256 + threadIdx.x) * 4;
    float4 v = *(const float4*)(W + idx);
    v.x = tf32rn(v.x); v.y = tf32rn(v.y); v.z = tf32rn(v.z); v.w = tf32rn(v.w);
    *(float4*)(d_Wr + idx) = v;
}

// ============================ K1: X'^T -> fp16 fragment-word layout ============================
__global__ void txpose_kernel(const float* __restrict__ x) {
    __shared__ float t[32][33];
    int n0 = blockIdx.x * 32, c0 = blockIdx.y * 32;
    int tx = threadIdx.x, ty = threadIdx.y;
#pragma unroll
    for (int u = 0; u < 4; u++) {
        int n = n0 + ty + u * 8;
        t[ty + u * 8][tx] = x[(long)n * DD + c0 + tx] * d_dis[n];
    }
    __syncthreads();
    int w = ty * 32 + tx;
    int fl = w >> 3, sub = w & 7, cq = sub >> 2, j = sub & 3;
    int l0 = cq * 16 + 2 * j;
    uint2 o;
    o.x = h2u(__float22half2_rn(make_float2(t[l0][fl],     t[l0 + 1][fl])));
    o.y = h2u(__float22half2_rn(make_float2(t[l0 + 8][fl], t[l0 + 9][fl])));
    int C = (n0 >> 4) + cq;
    ((uint2*)d_xTh)[(C * 256 + c0 + fl) * 4 + j] = o;
}

// ============================ K2: GEMM1 (fp16) part[ks] = adj[m0:,ksK] @ X'[ksK,:] ============================
// 256 threads, 8 warps in 2x4 grid, warp tile 64x64, acc = 128 regs.
__global__ void __launch_bounds__(256, 1) gemm1_kernel() {
    extern __shared__ char smem[];
    const uint32_t sbase = smem_u32(smem);
    const int tid = threadIdx.x, lane = tid & 31, wid = tid >> 5;
    const int wm = wid & 1, wn = wid >> 1;          // 2x4 warp grid, warp tile 64x64
    const int g4 = lane >> 2, c4 = lane & 3;
    const int ks = blockIdx.x & 1;
    const long m0 = (long)(blockIdx.x >> 1) * 128;
    const int NK = 128;                              // 4096 / 32

    const char* asrc = ((const char*)d_adjh) + m0 * 16384 + (long)ks * 8192;
    const char* bsrc = ((const char*)d_xTh) + (long)ks * 2097152;

    // per-thread hoisted lds bases (stage 0)
    const uint32_t aB = sbase + (uint32_t)((wm * 64 + g4) * 32 + c4 * 8);
    const uint32_t bB = sbase + 8192u + (uint32_t)((wn * 64 + g4) * 32 + c4 * 8);

    // cp.async decode: A word w: c=w>>8, m=(w>>1)&127, jh=w&1 ; dst = As + w*16
    const int a_c0 = 0, a_m0 = (tid >> 1) & 127, a_jh0 = tid & 1;
    (void)a_c0;

    float acc[4][8][4];
#pragma unroll
    for (int f = 0; f < 4; f++)
#pragma unroll
        for (int g = 0; g < 8; g++)
#pragma unroll
            for (int q = 0; q < 4; q++) acc[f][g][q] = 0.f;

    auto load_stage = [&](uint32_t soff, int kt) {
        const uint32_t As = sbase + soff;
        const uint32_t Bs = As + 8192;
        // A: 512 words, 2 per thread
#pragma unroll
        for (int u = 0; u < 2; u++) {
            int w = tid + u * 256;
            int c = w >> 8, m = (w >> 1) & 127, jh = w & 1;
            cpa16(As + (uint32_t)w * 16,
                  asrc + (long)m * 16384 + kt * 64 + c * 32 + jh * 16);
        }
        // B: 1024 words, 4 per thread (contiguous 16KB)
#pragma unroll
        for (int u = 0; u < 4; u++) {
            int w = tid + u * 256;
            cpa16(Bs + (uint32_t)w * 16, bsrc + (long)kt * 16384 + (long)w * 16);
        }
    };

    load_stage(0, 0);              CPA_COMMIT();
    load_stage(STAGE1_BYTES, 1);   CPA_COMMIT();

    uint32_t soff = 0;                         // stage being computed
    uint32_t loff = 2 * STAGE1_BYTES;          // stage being loaded

#pragma unroll 1
    for (int kt = 0; kt < NK; kt++) {
        CPA_WAIT(1);
        __syncthreads();
        if (kt + 2 < NK) load_stage(loff, kt + 2);
        CPA_COMMIT();
        loff = (loff == 2 * STAGE1_BYTES) ? 0 : loff + STAGE1_BYTES;

        const uint32_t aS = aB + soff;
        const uint32_t bS = bB + soff;
        soff = (soff == 2 * STAGE1_BYTES) ? 0 : soff + STAGE1_BYTES;

        // two K=16 chunks per stage
#pragma unroll
        for (int c = 0; c < 2; c++) {
            uint32_t b[8][2];
#pragma unroll
            for (int g = 0; g < 8; g++)
                lds64(b[g][0], b[g][1], bS + c * 8192 + g * 256);
#pragma unroll
            for (int f = 0; f < 4; f++) {
                uint32_t a0, a1, a2, a3;
                lds64(a0, a2, aS + c * 4096 + f * 512);
                lds64(a1, a3, aS + c * 4096 + f * 512 + 256);
#pragma unroll
                for (int g = 0; g < 8; g++)
                    mma16(acc[f][g], a0, a1, a2, a3, b[g][0], b[g][1]);
            }
        }
    }

    // epilogue: write split-K partials (fp32)
    float* pbase = d_part + (long)ks * NN * DD;
#pragma unroll
    for (int f = 0; f < 4; f++) {
        int row = wm * 64 + f * 16 + g4;
#pragma unroll
        for (int g = 0; g < 8; g++) {
            int col = wn * 64 + g * 8 + c4 * 2;
            float2 lo = make_float2(acc[f][g][0], acc[f][g][1]);
            float2 hi = make_float2(acc[f][g][2], acc[f][g][3]);
            *(float2*)(pbase + (m0 + row) * DD + col) = lo;
            *(float2*)(pbase + (m0 + row + 8) * DD + col) = hi;
        }
    }
}

// ============================================================================
// GEMM2 core (tf32, proven): warp tile 32x64, k4-interleaved fp32 SMEM.
// ============================================================================
template <int AROWS>
DINLINE void compute_stage2(const float* __restrict__ A, const float* __restrict__ B,
                            int mbase, int wn, int lane, float acc[2][8][4]) {
    const int g4 = lane >> 2;
    const int c4 = lane & 3;
#pragma unroll
    for (int k8 = 0; k8 < 4; k8++) {
        const int k4a = k8 * 2, k4b = k8 * 2 + 1;
        uint32_t b[8][2];
#pragma unroll
        for (int g = 0; g < 8; g++) {
            int n = wn * 64 + g * 8 + g4;
            b[g][0] = fbits(B[(k4a * 256 + n) * 4 + c4]);
            b[g][1] = fbits(B[(k4b * 256 + n) * 4 + c4]);
        }
#pragma unroll
        for (int f = 0; f < 2; f++) {
            int m = mbase + f * 16 + g4;
            uint32_t a0 = fbits(A[(k4a * AROWS + m) * 4 + c4]);
            uint32_t a1 = fbits(A[(k4a * AROWS + m + 8) * 4 + c4]);
            uint32_t a2 = fbits(A[(k4b * AROWS + m) * 4 + c4]);
            uint32_t a3 = fbits(A[(k4b * AROWS + m + 8) * 4 + c4]);
#pragma unroll
            for (int g = 0; g < 8; g++)
                mma8(acc[f][g], a0, a1, a2, a3, b[g][0], b[g][1]);
        }
    }
}

// ============================ K3: GEMM2 out = relu(diag(d) * ((part0+part1+diag(d)x) @ Wr^T)) ============================
__global__ void __launch_bounds__(256, 1) gemm2_kernel(const float* __restrict__ x,
                                                       float* __restrict__ out) {
    extern __shared__ float smemf[];
    const int tid = threadIdx.x, lane = tid & 31, wid = tid >> 5;
    const int wm = wid & 1, wn = wid >> 1;            // 2x4 warp grid
    const long m0 = (long)blockIdx.x * 64;
    const int j = tid & 7, r = tid >> 3;              // r: 0..31

    float acc[2][8][4];
#pragma unroll
    for (int f = 0; f < 2; f++)
#pragma unroll
        for (int g = 0; g < 8; g++)
#pragma unroll
            for (int q = 0; q < 4; q++) acc[f][g][q] = 0.f;

    float* As = smemf;                 // [8][64][4]
    float* Bs = smemf + 64 * 32;       // [8][256][4]
    const uint32_t bbase = smem_u32(Bs);

#pragma unroll 1
    for (int st = 0; st < 8; st++) {
        const int k0 = st * 32;
        __syncthreads();
#pragma unroll
        for (int u = 0; u < 8; u++) {
            int n = r + u * 32;
            cpa16(bbase + (uint32_t)((j * 256 + n) * 16), d_Wr + (long)n * DD + k0 + j * 4);
        }
        CPA_COMMIT();
#pragma unroll
        for (int u = 0; u < 2; u++) {
            int row = r + u * 32;
            long i = m0 + row;
            float di = d_dis[i];
            float4 p0 = *(const float4*)(d_part + i * DD + k0 + j * 4);
            float4 p1 = *(const float4*)(d_part + (long)NN * DD + i * DD + k0 + j * 4);
            float4 xv = *(const float4*)(x + i * DD + k0 + j * 4);
            float4 v;
            v.x = tf32rn(p0.x + p1.x + di * xv.x);
            v.y = tf32rn(p0.y + p1.y + di * xv.y);
            v.z = tf32rn(p0.z + p1.z + di * xv.z);
            v.w = tf32rn(p0.w + p1.w + di * xv.w);
            *(float4*)(As + (j * 64 + row) * 4) = v;
        }
        CPA_WAIT(0);
        __syncthreads();
        compute_stage2<64>(As, Bs, wm * 32, wn, lane, acc);
    }

#pragma unroll
    for (int f = 0; f < 2; f++) {
        int row = wm * 32 + f * 16 + (lane >> 2);
        float d0 = d_dis[m0 + row];
        float d8 = d_dis[m0 + row + 8];
#pragma unroll
        for (int g = 0; g < 8; g++) {
            int col = wn * 64 + g * 8 + (lane & 3) * 2;
            float2 lo, hi;
            lo.x = fmaxf(d0 * acc[f][g][0], 0.f);
            lo.y = fmaxf(d0 * acc[f][g][1], 0.f);
            hi.x = fmaxf(d8 * acc[f][g][2], 0.f);
            hi.y = fmaxf(d8 * acc[f][g][3], 0.f);
            *(float2*)(out + (m0 + row) * DD + col) = lo;
            *(float2*)(out + (m0 + row + 8) * DD + col) = hi;
        }
    }
}

// ============================ host ============================
extern "C" void kernel_launch(void* const* d_in, const int* in_sizes, int n_in,
                              void* d_out, int out_size) {
    const float* x   = (const float*)d_in[0];   // [8192, 256]
    const float* adj = (const float*)d_in[1];   // [8192, 8192]
    const float* W   = (const float*)d_in[2];   // [256, 256]
    float* out = (float*)d_out;

    cudaFuncSetAttribute(gemm1_kernel, cudaFuncAttributeMaxDynamicSharedMemorySize, SMEM1_BYTES);
    cudaFuncSetAttribute(gemm2_kernel, cudaFuncAttributeMaxDynamicSharedMemorySize, SMEM2_BYTES);

    prepass_kernel<<<NN, 256>>>(adj);
    wcopy_kernel<<<DD * DD / 1024, 256>>>(W);
    txpose_kernel<<<dim3(NN / 32, DD / 32), dim3(32, 8)>>>(x);
    gemm1_kernel<<<128, 256, SMEM1_BYTES>>>();
    gemm2_kernel<<<128, 256, SMEM2_BYTES>>>(x, out);
}

// round 7
// speedup vs baseline: 2.5779x; 1.0858x over previous
#include <cuda_runtime.h>
#include <cuda_fp16.h>
#include <cstdint>

#define DINLINE __device__ __forceinline__

// ============================ helpers ============================
DINLINE uint32_t smem_u32(const void* p) {
    uint32_t a;
    asm("{ .reg .u64 t; cvta.to.shared.u64 t, %1; cvt.u32.u64 %0, t; }" : "=r"(a) : "l"(p));
    return a;
}

DINLINE void cpa16(uint32_t dst, const void* src) {
    asm volatile("cp.async.cg.shared.global [%0], [%1], 16;"
                 :: "r"(dst), "l"(__cvta_generic_to_global(src)) : "memory");
}
#define CPA_COMMIT() asm volatile("cp.async.commit_group;" ::: "memory")
#define CPA_WAIT(n)  asm volatile("cp.async.wait_group %0;" :: "n"(n) : "memory")

// m16n8k16 fp16 HMMA, fp32 accumulate (target-portable, sm_80+)
DINLINE void mma16(float* d, uint32_t a0, uint32_t a1, uint32_t a2, uint32_t a3,
                   uint32_t b0, uint32_t b1) {
    asm volatile("mma.sync.aligned.m16n8k16.row.col.f32.f16.f16.f32 "
                 "{%0,%1,%2,%3}, {%4,%5,%6,%7}, {%8,%9}, {%0,%1,%2,%3};"
                 : "+f"(d[0]), "+f"(d[1]), "+f"(d[2]), "+f"(d[3])
                 : "r"(a0), "r"(a1), "r"(a2), "r"(a3), "r"(b0), "r"(b1));
}

// m16n8k8 tf32 HMMA (kept for gemm2)
DINLINE void mma8(float* d, uint32_t a0, uint32_t a1, uint32_t a2, uint32_t a3,
                  uint32_t b0, uint32_t b1) {
    asm volatile("mma.sync.aligned.m16n8k8.row.col.f32.tf32.tf32.f32 "
                 "{%0,%1,%2,%3}, {%4,%5,%6,%7}, {%8,%9}, {%0,%1,%2,%3};"
                 : "+f"(d[0]), "+f"(d[1]), "+f"(d[2]), "+f"(d[3])
                 : "r"(a0), "r"(a1), "r"(a2), "r"(a3), "r"(b0), "r"(b1));
}

DINLINE void lds64(uint32_t& lo, uint32_t& hi, uint32_t addr) {
    asm volatile("ld.shared.v2.b32 {%0,%1}, [%2];" : "=r"(lo), "=r"(hi) : "r"(addr));
}

// round-to-nearest tf32
DINLINE float tf32rn(float f) {
    uint32_t o;
    asm("cvt.rna.tf32.f32 %0, %1;" : "=r"(o) : "f"(f));
    return __uint_as_float(o);
}
DINLINE uint32_t fbits(float f) { return __float_as_uint(f); }
DINLINE uint32_t h2u(__half2 h) { return *(uint32_t*)&h; }

// ============================ constants ============================
static constexpr int NN = 8192;
static constexpr int DD = 256;

// GEMM1 (fp16): BM=128, BN=256, BK=32, 3 stages, 256 threads (8 warps, 2x4, warp tile 64x64)
// stage = A 8KB + B 16KB = 24KB
static constexpr int STAGE1_BYTES = 24576;
static constexpr int SMEM1_BYTES  = 3 * STAGE1_BYTES;           // 73728
// GEMM2 (tf32): BM=64, BN=256, BK=32 single-buffer, 256 threads
static constexpr int SMEM2_BYTES  = (64 + 256) * 32 * 4;        // 40960

// scratch (allocation-free contract: __device__ globals)
__device__ float d_dis[NN];                    // (1 + rowsum(adj))^{-1/2}
__device__ uint4 d_adjh[(long)NN * NN / 8];    // adj as fp16, fragment-word layout (128MB)
__device__ uint4 d_xTh[(long)NN * DD / 8];     // X'^T as fp16, fragment-word layout (4MB)
__device__ float d_part[2L * NN * DD];         // split-K partials of adj @ X'
__device__ float d_Wr[DD * DD];                // tf32rn(W)

// ============================================================================
// K0: fused rowsum + adj->fp16 conversion into fragment-word layout.
// ============================================================================
__global__ void prepass_kernel(const float* __restrict__ adj) {
    __shared__ float red[256];
    const long m = blockIdx.x;
    const int t = threadIdx.x, lane = t & 31;
    const float4* row = (const float4*)(adj + m * (long)NN);   // 2048 float4
    uint4* outrow = d_adjh + m * 1024;
    float s = 0.f;
#pragma unroll
    for (int u = 0; u < 8; u++) {
        int fi = u * 256 + t;                 // float4 index, covers k = 4*fi..4*fi+3
        float4 v = row[fi];
        s += (v.x + v.y) + (v.z + v.w);
        float px = __shfl_xor_sync(0xFFFFFFFFu, v.x, 2);
        float py = __shfl_xor_sync(0xFFFFFFFFu, v.y, 2);
        float pz = __shfl_xor_sync(0xFFFFFFFFu, v.z, 2);
        float pw = __shfl_xor_sync(0xFFFFFFFFu, v.w, 2);
        if ((lane & 2) == 0) {
            uint4 o;
            o.x = h2u(__float22half2_rn(make_float2(v.x, v.y)));
            o.y = h2u(__float22half2_rn(make_float2(px, py)));
            o.z = h2u(__float22half2_rn(make_float2(v.z, v.w)));
            o.w = h2u(__float22half2_rn(make_float2(pz, pw)));
            int chunk = fi >> 2, q = fi & 1;
            outrow[chunk * 2 + q] = o;
        }
    }
    red[t] = s;
    __syncthreads();
    for (int o = 128; o > 0; o >>= 1) {
        if (t < o) red[t] += red[t + o];
        __syncthreads();
    }
    if (t == 0) d_dis[m] = rsqrtf(1.0f + red[0]);
}

// ============================ K0b: W -> tf32rn copy (for gemm2) ============================
__global__ void wcopy_kernel(const float* __restrict__ W) {
    int idx = (blockIdx.x * 256 + threadIdx.x) * 4;
    float4 v = *(const float4*)(W + idx);
    v.x = tf32rn(v.x); v.y = tf32rn(v.y); v.z = tf32rn(v.z); v.w = tf32rn(v.w);
    *(float4*)(d_Wr + idx) = v;
}

// ============================ K1: X'^T -> fp16 fragment-word layout ============================
__global__ void txpose_kernel(const float* __restrict__ x) {
    __shared__ float t[32][33];
    int n0 = blockIdx.x * 32, c0 = blockIdx.y * 32;
    int tx = threadIdx.x, ty = threadIdx.y;
#pragma unroll
    for (int u = 0; u < 4; u++) {
        int n = n0 + ty + u * 8;
        t[ty + u * 8][tx] = x[(long)n * DD + c0 + tx] * d_dis[n];
    }
    __syncthreads();
    int w = ty * 32 + tx;
    int fl = w >> 3, sub = w & 7, cq = sub >> 2, j = sub & 3;
    int l0 = cq * 16 + 2 * j;
    uint2 o;
    o.x = h2u(__float22half2_rn(make_float2(t[l0][fl],     t[l0 + 1][fl])));
    o.y = h2u(__float22half2_rn(make_float2(t[l0 + 8][fl], t[l0 + 9][fl])));
    int C = (n0 >> 4) + cq;
    ((uint2*)d_xTh)[(C * 256 + c0 + fl) * 4 + j] = o;
}

// ============================ fragment buffers for gemm1 ============================
struct Frag {
    uint32_t a[4][4];
    uint32_t b[8][2];
};

DINLINE void prefetch_frag(Frag& F, uint32_t aAddr, uint32_t bAddr) {
#pragma unroll
    for (int g = 0; g < 8; g++)
        lds64(F.b[g][0], F.b[g][1], bAddr + g * 256);
#pragma unroll
    for (int f = 0; f < 4; f++) {
        lds64(F.a[f][0], F.a[f][2], aAddr + f * 512);
        lds64(F.a[f][1], F.a[f][3], aAddr + f * 512 + 256);
    }
}

DINLINE void mma_frag(float acc[4][8][4], const Frag& F) {
#pragma unroll
    for (int f = 0; f < 4; f++)
#pragma unroll
        for (int g = 0; g < 8; g++)
            mma16(acc[f][g], F.a[f][0], F.a[f][1], F.a[f][2], F.a[f][3],
                  F.b[g][0], F.b[g][1]);
}

// ============================ K2: GEMM1 (fp16) part[ks] = adj[m0:,ksK] @ X'[ksK,:] ============================
// 256 threads, 8 warps in 2x4 grid, warp tile 64x64, register-pipelined fragments.
__global__ void __launch_bounds__(256, 1) gemm1_kernel() {
    extern __shared__ char smem[];
    const uint32_t sbase = smem_u32(smem);
    const int tid = threadIdx.x, lane = tid & 31, wid = tid >> 5;
    const int wm = wid & 1, wn = wid >> 1;          // 2x4 warp grid, warp tile 64x64
    const int g4 = lane >> 2, c4 = lane & 3;
    const int ks = blockIdx.x & 1;
    const long m0 = (long)(blockIdx.x >> 1) * 128;
    const int NK = 128;                              // 4096 / 32

    const char* asrc = ((const char*)d_adjh) + m0 * 16384 + (long)ks * 8192;
    const char* bsrc = ((const char*)d_xTh) + (long)ks * 2097152;

    // per-thread hoisted lds bases (stage 0)
    const uint32_t aB = sbase + (uint32_t)((wm * 64 + g4) * 32 + c4 * 8);
    const uint32_t bB = sbase + 8192u + (uint32_t)((wn * 64 + g4) * 32 + c4 * 8);

    float acc[4][8][4];
#pragma unroll
    for (int f = 0; f < 4; f++)
#pragma unroll
        for (int g = 0; g < 8; g++)
#pragma unroll
            for (int q = 0; q < 4; q++) acc[f][g][q] = 0.f;

    auto load_stage = [&](uint32_t soff_, int kt) {
        const uint32_t As = sbase + soff_;
        const uint32_t Bs = As + 8192;
        // A: 512 words, 2 per thread
#pragma unroll
        for (int u = 0; u < 2; u++) {
            int w = tid + u * 256;
            int c = w >> 8, m = (w >> 1) & 127, jh = w & 1;
            cpa16(As + (uint32_t)w * 16,
                  asrc + (long)m * 16384 + kt * 64 + c * 32 + jh * 16);
        }
        // B: 1024 words, 4 per thread (contiguous 16KB)
#pragma unroll
        for (int u = 0; u < 4; u++) {
            int w = tid + u * 256;
            cpa16(Bs + (uint32_t)w * 16, bsrc + (long)kt * 16384 + (long)w * 16);
        }
    };

    load_stage(0, 0);              CPA_COMMIT();
    load_stage(STAGE1_BYTES, 1);   CPA_COMMIT();
    CPA_WAIT(1);
    __syncthreads();

    Frag F0, F1;
    prefetch_frag(F0, aB, bB);     // stage 0, chunk 0

    uint32_t soff = 0;                         // stage being computed
    uint32_t loff = 2 * STAGE1_BYTES;          // stage being loaded

#pragma unroll 1
    for (int kt = 0; kt < NK; kt++) {
        if (kt + 2 < NK) load_stage(loff, kt + 2);
        CPA_COMMIT();
        loff = (loff == 2 * STAGE1_BYTES) ? 0 : loff + STAGE1_BYTES;

        const uint32_t aS = aB + soff;
        const uint32_t bS = bB + soff;
        soff = (soff == 2 * STAGE1_BYTES) ? 0 : soff + STAGE1_BYTES;

        // chunk 0: mma F0 while prefetching chunk 1 into F1 (same stage, visible)
        prefetch_frag(F1, aS + 4096, bS + 8192);
        mma_frag(acc, F0);

        // make stage kt+1 visible to all threads; also fences slot reuse
        CPA_WAIT(1);
        __syncthreads();

        // chunk 1: mma F1 while prefetching next stage's chunk 0 into F0
        prefetch_frag(F0, aB + soff, bB + soff);
        mma_frag(acc, F1);
    }

    // epilogue: write split-K partials (fp32)
    float* pbase = d_part + (long)ks * NN * DD;
#pragma unroll
    for (int f = 0; f < 4; f++) {
        int row = wm * 64 + f * 16 + g4;
#pragma unroll
        for (int g = 0; g < 8; g++) {
            int col = wn * 64 + g * 8 + c4 * 2;
            float2 lo = make_float2(acc[f][g][0], acc[f][g][1]);
            float2 hi = make_float2(acc[f][g][2], acc[f][g][3]);
            *(float2*)(pbase + (m0 + row) * DD + col) = lo;
            *(float2*)(pbase + (m0 + row + 8) * DD + col) = hi;
        }
    }
}

// ============================================================================
// GEMM2 core (tf32, proven): warp tile 32x64, k4-interleaved fp32 SMEM.
// ============================================================================
template <int AROWS>
DINLINE void compute_stage2(const float* __restrict__ A, const float* __restrict__ B,
                            int mbase, int wn, int lane, float acc[2][8][4]) {
    const int g4 = lane >> 2;
    const int c4 = lane & 3;
#pragma unroll
    for (int k8 = 0; k8 < 4; k8++) {
        const int k4a = k8 * 2, k4b = k8 * 2 + 1;
        uint32_t b[8][2];
#pragma unroll
        for (int g = 0; g < 8; g++) {
            int n = wn * 64 + g * 8 + g4;
            b[g][0] = fbits(B[(k4a * 256 + n) * 4 + c4]);
            b[g][1] = fbits(B[(k4b * 256 + n) * 4 + c4]);
        }
#pragma unroll
        for (int f = 0; f < 2; f++) {
            int m = mbase + f * 16 + g4;
            uint32_t a0 = fbits(A[(k4a * AROWS + m) * 4 + c4]);
            uint32_t a1 = fbits(A[(k4a * AROWS + m + 8) * 4 + c4]);
            uint32_t a2 = fbits(A[(k4b * AROWS + m) * 4 + c4]);
            uint32_t a3 = fbits(A[(k4b * AROWS + m + 8) * 4 + c4]);
#pragma unroll
            for (int g = 0; g < 8; g++)
                mma8(acc[f][g], a0, a1, a2, a3, b[g][0], b[g][1]);
        }
    }
}

// ============================ K3: GEMM2 out = relu(diag(d) * ((part0+part1+diag(d)x) @ Wr^T)) ============================
__global__ void __launch_bounds__(256, 1) gemm2_kernel(const float* __restrict__ x,
                                                       float* __restrict__ out) {
    extern __shared__ float smemf[];
    const int tid = threadIdx.x, lane = tid & 31, wid = tid >> 5;
    const int wm = wid & 1, wn = wid >> 1;            // 2x4 warp grid
    const long m0 = (long)blockIdx.x * 64;
    const int j = tid & 7, r = tid >> 3;              // r: 0..31

    float acc[2][8][4];
#pragma unroll
    for (int f = 0; f < 2; f++)
#pragma unroll
        for (int g = 0; g < 8; g++)
#pragma unroll
            for (int q = 0; q < 4; q++) acc[f][g][q] = 0.f;

    float* As = smemf;                 // [8][64][4]
    float* Bs = smemf + 64 * 32;       // [8][256][4]
    const uint32_t bbase = smem_u32(Bs);

#pragma unroll 1
    for (int st = 0; st < 8; st++) {
        const int k0 = st * 32;
        __syncthreads();
#pragma unroll
        for (int u = 0; u < 8; u++) {
            int n = r + u * 32;
            cpa16(bbase + (uint32_t)((j * 256 + n) * 16), d_Wr + (long)n * DD + k0 + j * 4);
        }
        CPA_COMMIT();
#pragma unroll
        for (int u = 0; u < 2; u++) {
            int row = r + u * 32;
            long i = m0 + row;
            float di = d_dis[i];
            float4 p0 = *(const float4*)(d_part + i * DD + k0 + j * 4);
            float4 p1 = *(const float4*)(d_part + (long)NN * DD + i * DD + k0 + j * 4);
            float4 xv = *(const float4*)(x + i * DD + k0 + j * 4);
            float4 v;
            v.x = tf32rn(p0.x + p1.x + di * xv.x);
            v.y = tf32rn(p0.y + p1.y + di * xv.y);
            v.z = tf32rn(p0.z + p1.z + di * xv.z);
            v.w = tf32rn(p0.w + p1.w + di * xv.w);
            *(float4*)(As + (j * 64 + row) * 4) = v;
        }
        CPA_WAIT(0);
        __syncthreads();
        compute_stage2<64>(As, Bs, wm * 32, wn, lane, acc);
    }

#pragma unroll
    for (int f = 0; f < 2; f++) {
        int row = wm * 32 + f * 16 + (lane >> 2);
        float d0 = d_dis[m0 + row];
        float d8 = d_dis[m0 + row + 8];
#pragma unroll
        for (int g = 0; g < 8; g++) {
            int col = wn * 64 + g * 8 + (lane & 3) * 2;
            float2 lo, hi;
            lo.x = fmaxf(d0 * acc[f][g][0], 0.f);
            lo.y = fmaxf(d0 * acc[f][g][1], 0.f);
            hi.x = fmaxf(d8 * acc[f][g][2], 0.f);
            hi.y = fmaxf(d8 * acc[f][g][3], 0.f);
            *(float2*)(out + (m0 + row) * DD + col) = lo;
            *(float2*)(out + (m0 + row + 8) * DD + col) = hi;
        }
    }
}

// ============================ host ============================
extern "C" void kernel_launch(void* const* d_in, const int* in_sizes, int n_in,
                              void* d_out, int out_size) {
    const float* x   = (const float*)d_in[0];   // [8192, 256]
    const float* adj = (const float*)d_in[1];   // [8192, 8192]
    const float* W   = (const float*)d_in[2];   // [256, 256]
    float* out = (float*)d_out;

    cudaFuncSetAttribute(gemm1_kernel, cudaFuncAttributeMaxDynamicSharedMemorySize, SMEM1_BYTES);
    cudaFuncSetAttribute(gemm2_kernel, cudaFuncAttributeMaxDynamicSharedMemorySize, SMEM2_BYTES);

    prepass_kernel<<<NN, 256>>>(adj);
    wcopy_kernel<<<DD * DD / 1024, 256>>>(W);
    txpose_kernel<<<dim3(NN / 32, DD / 32), dim3(32, 8)>>>(x);
    gemm1_kernel<<<128, 256, SMEM1_BYTES>>>();
    gemm2_kernel<<<128, 256, SMEM2_BYTES>>>(x, out);
}

// round 8
// speedup vs baseline: 2.6320x; 1.0210x over previous
#include <cuda_runtime.h>
#include <cuda_fp16.h>
#include <cstdint>

#define DINLINE __device__ __forceinline__

// ============================ helpers ============================
DINLINE uint32_t smem_u32(const void* p) {
    uint32_t a;
    asm("{ .reg .u64 t; cvta.to.shared.u64 t, %1; cvt.u32.u64 %0, t; }" : "=r"(a) : "l"(p));
    return a;
}

DINLINE void cpa16(uint32_t dst, const void* src) {
    asm volatile("cp.async.cg.shared.global [%0], [%1], 16;"
                 :: "r"(dst), "l"(__cvta_generic_to_global(src)) : "memory");
}
#define CPA_COMMIT() asm volatile("cp.async.commit_group;" ::: "memory")
#define CPA_WAIT(n)  asm volatile("cp.async.wait_group %0;" :: "n"(n) : "memory")

// m16n8k16 fp16 HMMA, fp32 accumulate (target-portable, sm_80+)
DINLINE void mma16(float* d, uint32_t a0, uint32_t a1, uint32_t a2, uint32_t a3,
                   uint32_t b0, uint32_t b1) {
    asm volatile("mma.sync.aligned.m16n8k16.row.col.f32.f16.f16.f32 "
                 "{%0,%1,%2,%3}, {%4,%5,%6,%7}, {%8,%9}, {%0,%1,%2,%3};"
                 : "+f"(d[0]), "+f"(d[1]), "+f"(d[2]), "+f"(d[3])
                 : "r"(a0), "r"(a1), "r"(a2), "r"(a3), "r"(b0), "r"(b1));
}

// m16n8k8 tf32 HMMA (kept for gemm2)
DINLINE void mma8(float* d, uint32_t a0, uint32_t a1, uint32_t a2, uint32_t a3,
                  uint32_t b0, uint32_t b1) {
    asm volatile("mma.sync.aligned.m16n8k8.row.col.f32.tf32.tf32.f32 "
                 "{%0,%1,%2,%3}, {%4,%5,%6,%7}, {%8,%9}, {%0,%1,%2,%3};"
                 : "+f"(d[0]), "+f"(d[1]), "+f"(d[2]), "+f"(d[3])
                 : "r"(a0), "r"(a1), "r"(a2), "r"(a3), "r"(b0), "r"(b1));
}

DINLINE void lds64(uint32_t& lo, uint32_t& hi, uint32_t addr) {
    asm volatile("ld.shared.v2.b32 {%0,%1}, [%2];" : "=r"(lo), "=r"(hi) : "r"(addr));
}

// round-to-nearest tf32
DINLINE float tf32rn(float f) {
    uint32_t o;
    asm("cvt.rna.tf32.f32 %0, %1;" : "=r"(o) : "f"(f));
    return __uint_as_float(o);
}
DINLINE uint32_t fbits(float f) { return __float_as_uint(f); }
DINLINE uint32_t h2u(__half2 h) { return *(uint32_t*)&h; }

// ============================ constants ============================
static constexpr int NN = 8192;
static constexpr int DD = 256;

// GEMM1 (fp16): BM=64, BN=256, BK=32, 4 stages, 128 threads (4 warps, 1x4, warp tile 64x64)
// stage = A 4KB + B 16KB = 20KB
static constexpr int STAGE1_BYTES = 20480;
static constexpr int SMEM1_BYTES  = 4 * STAGE1_BYTES;           // 81920 (2 CTAs/SM -> 160KB)
// GEMM2 (tf32): BM=64, BN=256, BK=32 single-buffer, 256 threads
static constexpr int SMEM2_BYTES  = (64 + 256) * 32 * 4;        // 40960

// scratch (allocation-free contract: __device__ globals)
__device__ float d_dis[NN];                    // (1 + rowsum(adj))^{-1/2}
__device__ uint4 d_adjh[(long)NN * NN / 8];    // adj as fp16, fragment-word layout (128MB)
__device__ uint4 d_xTh[(long)NN * DD / 8];     // X'^T as fp16, fragment-word layout (4MB)
__device__ float d_part[2L * NN * DD];         // split-K partials of adj @ X'
__device__ float d_Wr[DD * DD];                // tf32rn(W)

// ============================================================================
// K0: fused rowsum + adj->fp16 conversion into fragment-word layout.
// ============================================================================
__global__ void prepass_kernel(const float* __restrict__ adj) {
    __shared__ float red[256];
    const long m = blockIdx.x;
    const int t = threadIdx.x, lane = t & 31;
    const float4* row = (const float4*)(adj + m * (long)NN);   // 2048 float4
    uint4* outrow = d_adjh + m * 1024;
    float s = 0.f;
#pragma unroll
    for (int u = 0; u < 8; u++) {
        int fi = u * 256 + t;                 // float4 index, covers k = 4*fi..4*fi+3
        float4 v = row[fi];
        s += (v.x + v.y) + (v.z + v.w);
        float px = __shfl_xor_sync(0xFFFFFFFFu, v.x, 2);
        float py = __shfl_xor_sync(0xFFFFFFFFu, v.y, 2);
        float pz = __shfl_xor_sync(0xFFFFFFFFu, v.z, 2);
        float pw = __shfl_xor_sync(0xFFFFFFFFu, v.w, 2);
        if ((lane & 2) == 0) {
            uint4 o;
            o.x = h2u(__float22half2_rn(make_float2(v.x, v.y)));
            o.y = h2u(__float22half2_rn(make_float2(px, py)));
            o.z = h2u(__float22half2_rn(make_float2(v.z, v.w)));
            o.w = h2u(__float22half2_rn(make_float2(pz, pw)));
            int chunk = fi >> 2, q = fi & 1;
            outrow[chunk * 2 + q] = o;
        }
    }
    red[t] = s;
    __syncthreads();
    for (int o = 128; o > 0; o >>= 1) {
        if (t < o) red[t] += red[t + o];
        __syncthreads();
    }
    if (t == 0) d_dis[m] = rsqrtf(1.0f + red[0]);
}

// ============================ K0b: W -> tf32rn copy (for gemm2) ============================
__global__ void wcopy_kernel(const float* __restrict__ W) {
    int idx = (blockIdx.x * 256 + threadIdx.x) * 4;
    float4 v = *(const float4*)(W + idx);
    v.x = tf32rn(v.x); v.y = tf32rn(v.y); v.z = tf32rn(v.z); v.w = tf32rn(v.w);
    *(float4*)(d_Wr + idx) = v;
}

// ============================ K1: X'^T -> fp16 fragment-word layout ============================
__global__ void txpose_kernel(const float* __restrict__ x) {
    __shared__ float t[32][33];
    int n0 = blockIdx.x * 32, c0 = blockIdx.y * 32;
    int tx = threadIdx.x, ty = threadIdx.y;
#pragma unroll
    for (int u = 0; u < 4; u++) {
        int n = n0 + ty + u * 8;
        t[ty + u * 8][tx] = x[(long)n * DD + c0 + tx] * d_dis[n];
    }
    __syncthreads();
    int w = ty * 32 + tx;
    int fl = w >> 3, sub = w & 7, cq = sub >> 2, j = sub & 3;
    int l0 = cq * 16 + 2 * j;
    uint2 o;
    o.x = h2u(__float22half2_rn(make_float2(t[l0][fl],     t[l0 + 1][fl])));
    o.y = h2u(__float22half2_rn(make_float2(t[l0 + 8][fl], t[l0 + 9][fl])));
    int C = (n0 >> 4) + cq;
    ((uint2*)d_xTh)[(C * 256 + c0 + fl) * 4 + j] = o;
}

// ============================ fragment buffers for gemm1 ============================
struct Frag {
    uint32_t a[4][4];
    uint32_t b[8][2];
};

DINLINE void prefetch_frag(Frag& F, uint32_t aAddr, uint32_t bAddr) {
#pragma unroll
    for (int g = 0; g < 8; g++)
        lds64(F.b[g][0], F.b[g][1], bAddr + g * 256);
#pragma unroll
    for (int f = 0; f < 4; f++) {
        lds64(F.a[f][0], F.a[f][2], aAddr + f * 512);
        lds64(F.a[f][1], F.a[f][3], aAddr + f * 512 + 256);
    }
}

DINLINE void mma_frag(float acc[4][8][4], const Frag& F) {
#pragma unroll
    for (int f = 0; f < 4; f++)
#pragma unroll
        for (int g = 0; g < 8; g++)
            mma16(acc[f][g], F.a[f][0], F.a[f][1], F.a[f][2], F.a[f][3],
                  F.b[g][0], F.b[g][1]);
}

// ============================ K2: GEMM1 (fp16) part[ks] = adj[m0:,ksK] @ X'[ksK,:] ============================
// 128 threads, 4 warps (1x4), warp tile 64x64, BM=64, 2 CTAs/SM, 4-stage pipeline.
__global__ void __launch_bounds__(128, 2) gemm1_kernel() {
    extern __shared__ char smem[];
    const uint32_t sbase = smem_u32(smem);
    const int tid = threadIdx.x, lane = tid & 31, wid = tid >> 5;
    const int wn = wid;                              // 1x4 warp grid, warp tile 64x64
    const int g4 = lane >> 2, c4 = lane & 3;
    const int ks = blockIdx.x & 1;
    const long m0 = (long)(blockIdx.x >> 1) * 64;
    const int NK = 128;                              // 4096 / 32

    const char* asrc = ((const char*)d_adjh) + m0 * 16384 + (long)ks * 8192;
    const char* bsrc = ((const char*)d_xTh) + (long)ks * 2097152;

    // per-thread hoisted lds bases (stage 0); A row stride 32B, 64 rows
    const uint32_t aB = sbase + (uint32_t)(g4 * 32 + c4 * 8);
    const uint32_t bB = sbase + 4096u + (uint32_t)((wn * 64 + g4) * 32 + c4 * 8);

    float acc[4][8][4];
#pragma unroll
    for (int f = 0; f < 4; f++)
#pragma unroll
        for (int g = 0; g < 8; g++)
#pragma unroll
            for (int q = 0; q < 4; q++) acc[f][g][q] = 0.f;

    auto load_stage = [&](uint32_t soff_, int kt) {
        const uint32_t As = sbase + soff_;
        const uint32_t Bs = As + 4096;
        // A: 256 words, 2 per thread. word w: c=w>>7, m=(w>>1)&63, jh=w&1
#pragma unroll
        for (int u = 0; u < 2; u++) {
            int w = tid + u * 128;
            int c = w >> 7, m = (w >> 1) & 63, jh = w & 1;
            cpa16(As + (uint32_t)w * 16,
                  asrc + (long)m * 16384 + kt * 64 + c * 32 + jh * 16);
        }
        // B: 1024 words, 8 per thread (contiguous 16KB)
#pragma unroll
        for (int u = 0; u < 8; u++) {
            int w = tid + u * 128;
            cpa16(Bs + (uint32_t)w * 16, bsrc + (long)kt * 16384 + (long)w * 16);
        }
    };

    load_stage(0, 0);                  CPA_COMMIT();
    load_stage(STAGE1_BYTES, 1);       CPA_COMMIT();
    load_stage(2 * STAGE1_BYTES, 2);   CPA_COMMIT();
    CPA_WAIT(2);
    __syncthreads();

    Frag F0, F1;
    prefetch_frag(F0, aB, bB);         // stage 0, chunk 0

    uint32_t soff = 0;                         // stage being computed
    uint32_t loff = 3 * STAGE1_BYTES;          // stage being loaded

#pragma unroll 1
    for (int kt = 0; kt < NK; kt++) {
        if (kt + 3 < NK) load_stage(loff, kt + 3);
        CPA_COMMIT();
        loff = (loff == 3 * STAGE1_BYTES) ? 0 : loff + STAGE1_BYTES;

        const uint32_t aS = aB + soff;
        const uint32_t bS = bB + soff;
        soff = (soff == 3 * STAGE1_BYTES) ? 0 : soff + STAGE1_BYTES;

        // chunk 0: mma F0 while prefetching chunk 1 into F1 (same stage, visible)
        prefetch_frag(F1, aS + 2048, bS + 8192);
        mma_frag(acc, F0);

        // make stage kt+1 visible; <=2 groups may remain pending
        CPA_WAIT(2);
        __syncthreads();

        // chunk 1: mma F1 while prefetching next stage's chunk 0 into F0
        prefetch_frag(F0, aB + soff, bB + soff);
        mma_frag(acc, F1);
    }

    // epilogue: write split-K partials (fp32)
    float* pbase = d_part + (long)ks * NN * DD;
#pragma unroll
    for (int f = 0; f < 4; f++) {
        int row = f * 16 + g4;
#pragma unroll
        for (int g = 0; g < 8; g++) {
            int col = wn * 64 + g * 8 + c4 * 2;
            float2 lo = make_float2(acc[f][g][0], acc[f][g][1]);
            float2 hi = make_float2(acc[f][g][2], acc[f][g][3]);
            *(float2*)(pbase + (m0 + row) * DD + col) = lo;
            *(float2*)(pbase + (m0 + row + 8) * DD + col) = hi;
        }
    }
}

// ============================================================================
// GEMM2 core (tf32, proven): warp tile 32x64, k4-interleaved fp32 SMEM.
// ============================================================================
template <int AROWS>
DINLINE void compute_stage2(const float* __restrict__ A, const float* __restrict__ B,
                            int mbase, int wn, int lane, float acc[2][8][4]) {
    const int g4 = lane >> 2;
    const int c4 = lane & 3;
#pragma unroll
    for (int k8 = 0; k8 < 4; k8++) {
        const int k4a = k8 * 2, k4b = k8 * 2 + 1;
        uint32_t b[8][2];
#pragma unroll
        for (int g = 0; g < 8; g++) {
            int n = wn * 64 + g * 8 + g4;
            b[g][0] = fbits(B[(k4a * 256 + n) * 4 + c4]);
            b[g][1] = fbits(B[(k4b * 256 + n) * 4 + c4]);
        }
#pragma unroll
        for (int f = 0; f < 2; f++) {
            int m = mbase + f * 16 + g4;
            uint32_t a0 = fbits(A[(k4a * AROWS + m) * 4 + c4]);
            uint32_t a1 = fbits(A[(k4a * AROWS + m + 8) * 4 + c4]);
            uint32_t a2 = fbits(A[(k4b * AROWS + m) * 4 + c4]);
            uint32_t a3 = fbits(A[(k4b * AROWS + m + 8) * 4 + c4]);
#pragma unroll
            for (int g = 0; g < 8; g++)
                mma8(acc[f][g], a0, a1, a2, a3, b[g][0], b[g][1]);
        }
    }
}

// ============================ K3: GEMM2 out = relu(diag(d) * ((part0+part1+diag(d)x) @ Wr^T)) ============================
__global__ void __launch_bounds__(256, 1) gemm2_kernel(const float* __restrict__ x,
                                                       float* __restrict__ out) {
    extern __shared__ float smemf[];
    const int tid = threadIdx.x, lane = tid & 31, wid = tid >> 5;
    const int wm = wid & 1, wn = wid >> 1;            // 2x4 warp grid
    const long m0 = (long)blockIdx.x * 64;
    const int j = tid & 7, r = tid >> 3;              // r: 0..31

    float acc[2][8][4];
#pragma unroll
    for (int f = 0; f < 2; f++)
#pragma unroll
        for (int g = 0; g < 8; g++)
#pragma unroll
            for (int q = 0; q < 4; q++) acc[f][g][q] = 0.f;

    float* As = smemf;                 // [8][64][4]
    float* Bs = smemf + 64 * 32;       // [8][256][4]
    const uint32_t bbase = smem_u32(Bs);

#pragma unroll 1
    for (int st = 0; st < 8; st++) {
        const int k0 = st * 32;
        __syncthreads();
#pragma unroll
        for (int u = 0; u < 8; u++) {
            int n = r + u * 32;
            cpa16(bbase + (uint32_t)((j * 256 + n) * 16), d_Wr + (long)n * DD + k0 + j * 4);
        }
        CPA_COMMIT();
#pragma unroll
        for (int u = 0; u < 2; u++) {
            int row = r + u * 32;
            long i = m0 + row;
            float di = d_dis[i];
            float4 p0 = *(const float4*)(d_part + i * DD + k0 + j * 4);
            float4 p1 = *(const float4*)(d_part + (long)NN * DD + i * DD + k0 + j * 4);
            float4 xv = *(const float4*)(x + i * DD + k0 + j * 4);
            float4 v;
            v.x = tf32rn(p0.x + p1.x + di * xv.x);
            v.y = tf32rn(p0.y + p1.y + di * xv.y);
            v.z = tf32rn(p0.z + p1.z + di * xv.z);
            v.w = tf32rn(p0.w + p1.w + di * xv.w);
            *(float4*)(As + (j * 64 + row) * 4) = v;
        }
        CPA_WAIT(0);
        __syncthreads();
        compute_stage2<64>(As, Bs, wm * 32, wn, lane, acc);
    }

#pragma unroll
    for (int f = 0; f < 2; f++) {
        int row = wm * 32 + f * 16 + (lane >> 2);
        float d0 = d_dis[m0 + row];
        float d8 = d_dis[m0 + row + 8];
#pragma unroll
        for (int g = 0; g < 8; g++) {
            int col = wn * 64 + g * 8 + (lane & 3) * 2;
            float2 lo, hi;
            lo.x = fmaxf(d0 * acc[f][g][0], 0.f);
            lo.y = fmaxf(d0 * acc[f][g][1], 0.f);
            hi.x = fmaxf(d8 * acc[f][g][2], 0.f);
            hi.y = fmaxf(d8 * acc[f][g][3], 0.f);
            *(float2*)(out + (m0 + row) * DD + col) = lo;
            *(float2*)(out + (m0 + row + 8) * DD + col) = hi;
        }
    }
}

// ============================ host ============================
extern "C" void kernel_launch(void* const* d_in, const int* in_sizes, int n_in,
                              void* d_out, int out_size) {
    const float* x   = (const float*)d_in[0];   // [8192, 256]
    const float* adj = (const float*)d_in[1];   // [8192, 8192]
    const float* W   = (const float*)d_in[2];   // [256, 256]
    float* out = (float*)d_out;

    cudaFuncSetAttribute(gemm1_kernel, cudaFuncAttributeMaxDynamicSharedMemorySize, SMEM1_BYTES);
    cudaFuncSetAttribute(gemm2_kernel, cudaFuncAttributeMaxDynamicSharedMemorySize, SMEM2_BYTES);

    prepass_kernel<<<NN, 256>>>(adj);
    wcopy_kernel<<<DD * DD / 1024, 256>>>(W);
    txpose_kernel<<<dim3(NN / 32, DD / 32), dim3(32, 8)>>>(x);
    gemm1_kernel<<<256, 128, SMEM1_BYTES>>>();
    gemm2_kernel<<<128, 256, SMEM2_BYTES>>>(x, out);
}